// round 2
// baseline (speedup 1.0000x reference)
#include <cuda_runtime.h>
#include <math.h>
#include <stdint.h>

#define NB 16
#define NT 2048
#define NC 256
#define NF 256
#define NU 512
#define NMEL 80
#define NOUTC 592           // 2*NC + NMEL
#define KTOT 768            // NC * 3 taps
#define UM2CAP 8192
#define EPS 1e-5f

// ---------------- static device scratch (no allocations allowed) ----------------
__device__ int   g_starts[NB*NU];
__device__ int   g_dur[NB*NU];
__device__ int   g_nseg[NB];
__device__ int   g_umax;
__device__ float g_cgv[NB*NC];          // per-batch cond vector (cond_w @ g + cond_b)
__device__ float g_uc[NB*NC*NU];        // pooled content units (zero padded)
__device__ float g_up[NB*NC*NU];        // pooled pitch units
__device__ float g_x0[NB*NC*NU];        // (u_c + cond) * mask  -> conv1 input
__device__ float g_y [NB*NF*NU];        // conv output (relu applied), reused conv1/conv2
__device__ float g_x1[NB*NF*NU];        // LN1 output * mask -> conv2 input
__device__ float g_x2[NB*NF*NU];        // LN2 output * mask -> proj input
__device__ int   g_dpred[NB*NU];        // predicted durations (can be negative)
__device__ int   g_um2[NB*UM2CAP];      // frame -> unit-id mapping (sum semantics)

// ---------------- kernel 0: zero um2 + umax ----------------
__global__ void k_zero(int Tn) {
    int i = blockIdx.x * blockDim.x + threadIdx.x;
    if (i == 0) g_umax = 0;
    if (i < NB * Tn) g_um2[i] = 0;
}

// ---------------- kernel 1: per-batch run-length dedup ----------------
__global__ __launch_bounds__(1024) void k_dedup(const int* __restrict__ ph) {
    int b = blockIdx.x;
    const int* p = ph + (size_t)b * NT;
    __shared__ int sa[NT];
    __shared__ int sb[NT];
    int tid = threadIdx.x;
    for (int i = tid; i < NT; i += 1024)
        sa[i] = (i == 0) || (p[i] != p[i - 1]);
    __syncthreads();
    // inclusive scan, ping-pong Hillis-Steele
    int* a = sa; int* bb = sb;
    for (int off = 1; off < NT; off <<= 1) {
        for (int i = tid; i < NT; i += 1024) {
            int v = a[i];
            if (i >= off) v += a[i - off];
            bb[i] = v;
        }
        __syncthreads();
        int* t = a; a = bb; bb = t;
    }
    int ns = a[NT - 1];
    for (int i = tid; i < NT; i += 1024) {
        if ((i == 0) || (p[i] != p[i - 1])) {
            int sg = a[i] - 1;
            g_starts[b * NU + sg] = i;
        }
    }
    __syncthreads();
    for (int u = tid; u < NU; u += 1024) {
        if (u < ns) {
            int st = g_starts[b * NU + u];
            int en = (u + 1 < ns) ? g_starts[b * NU + u + 1] : NT;
            g_dur[b * NU + u] = en - st;
        } else {
            g_dur[b * NU + u] = 0;
        }
    }
    if (tid == 0) {
        g_nseg[b] = ns;
        atomicMax(&g_umax, ns);
    }
}

// ---------------- kernel 2: cond vector per batch ----------------
__global__ __launch_bounds__(256) void k_cond(const float* __restrict__ g,
                                              const float* __restrict__ cw,
                                              const float* __restrict__ cb) {
    int b = blockIdx.x;
    int c = threadIdx.x;
    __shared__ float gs[NC];
    gs[c] = g[(size_t)b * NC + c];
    __syncthreads();
    float acc = 0.f;
    const float* row = cw + (size_t)c * NC;
    #pragma unroll 8
    for (int gi = 0; gi < NC; gi++) acc += row[gi] * gs[gi];
    g_cgv[b * NC + c] = acc + cb[c];
}

// ---------------- kernel 3: mean pool frames->units (+ build x0) ----------------
__global__ __launch_bounds__(256) void k_pool(const float* __restrict__ ec,
                                              const float* __restrict__ ep) {
    int b = blockIdx.y;
    int cc = blockIdx.x;          // 0..511 : 0..255 content, 256..511 pitch
    int ns = g_nseg[b];
    const float* src = (cc < NC) ? ec + ((size_t)b * NC + cc) * NT
                                 : ep + ((size_t)b * NC + (cc - NC)) * NT;
    __shared__ float row[NT];
    for (int i = threadIdx.x; i < NT; i += 256) row[i] = src[i];
    __syncthreads();
    float cond = (cc < NC) ? g_cgv[b * NC + cc] : 0.f;
    for (int u = threadIdx.x; u < NU; u += 256) {
        float m = 0.f;
        if (u < ns) {
            int st = g_starts[b * NU + u];
            int d  = g_dur[b * NU + u];
            float s = 0.f;
            for (int i = 0; i < d; i++) s += row[st + i];
            m = s / (float)d;
        }
        if (cc < NC) {
            g_uc[((size_t)b * NC + cc) * NU + u] = m;
            g_x0[((size_t)b * NC + cc) * NU + u] = (u < ns) ? (m + cond) : 0.f;
        } else {
            g_up[((size_t)b * NC + (cc - NC)) * NU + u] = m;
        }
    }
}

// ---------------- kernel 4: conv (as GEMM 256 x 512 x 768) + bias + relu ----------------
// phase 0: in = g_x0, phase 1: in = g_x1. Output always g_y.
__global__ __launch_bounds__(256) void k_conv(const float* __restrict__ W,
                                              const float* __restrict__ bias,
                                              int phase) {
    const float* X = phase ? g_x1 : g_x0;
    __shared__ float As[16][64];
    __shared__ float Bs[16][68];
    int b  = blockIdx.z;
    int f0 = blockIdx.y * 64;
    int u0 = blockIdx.x * 64;
    int tid = threadIdx.x;
    int tm = tid >> 4;        // 0..15
    int tn = tid & 15;        // 0..15
    const float* Xb = X + (size_t)b * NC * NU;

    float acc[4][4];
    #pragma unroll
    for (int i = 0; i < 4; i++)
        #pragma unroll
        for (int j = 0; j < 4; j++) acc[i][j] = 0.f;

    for (int k0 = 0; k0 < KTOT; k0 += 16) {
        // A load: W is (F, 768) row-major. As[kk][m] = W[f0+m][k0+kk]
        {
            int m  = tid >> 2;
            int kq = (tid & 3) * 4;
            float4 wv = *(const float4*)&W[(size_t)(f0 + m) * KTOT + k0 + kq];
            As[kq + 0][m] = wv.x;
            As[kq + 1][m] = wv.y;
            As[kq + 2][m] = wv.z;
            As[kq + 3][m] = wv.w;
        }
        // B load: Bs[kk][uu] = X[c][u0+uu+tap-1], kk = c*3+tap - k0
        {
            int kk   = tid >> 4;
            int kg   = k0 + kk;
            int c    = kg / 3;
            int tap  = kg - c * 3;
            const float* xr = Xb + (size_t)c * NU;
            int ub = u0 + tn * 4 + tap - 1;
            #pragma unroll
            for (int j = 0; j < 4; j++) {
                int pos = ub + j;
                Bs[kk][tn * 4 + j] = (pos >= 0 && pos < NU) ? xr[pos] : 0.f;
            }
        }
        __syncthreads();
        #pragma unroll
        for (int kk = 0; kk < 16; kk++) {
            float4 av = *(const float4*)&As[kk][tm * 4];
            float4 bv = *(const float4*)&Bs[kk][tn * 4];
            acc[0][0] += av.x * bv.x; acc[0][1] += av.x * bv.y;
            acc[0][2] += av.x * bv.z; acc[0][3] += av.x * bv.w;
            acc[1][0] += av.y * bv.x; acc[1][1] += av.y * bv.y;
            acc[1][2] += av.y * bv.z; acc[1][3] += av.y * bv.w;
            acc[2][0] += av.z * bv.x; acc[2][1] += av.z * bv.y;
            acc[2][2] += av.z * bv.z; acc[2][3] += av.z * bv.w;
            acc[3][0] += av.w * bv.x; acc[3][1] += av.w * bv.y;
            acc[3][2] += av.w * bv.z; acc[3][3] += av.w * bv.w;
        }
        __syncthreads();
    }
    #pragma unroll
    for (int i = 0; i < 4; i++) {
        int f = f0 + tm * 4 + i;
        float bs = bias[f];
        #pragma unroll
        for (int j = 0; j < 4; j++) {
            int u = u0 + tn * 4 + j;
            float v = acc[i][j] + bs;
            g_y[((size_t)b * NF + f) * NU + u] = fmaxf(v, 0.f);
        }
    }
}

// ---------------- kernel 5: channel layernorm + mask ----------------
// phase 0: out = g_x1 (after conv1), phase 1: out = g_x2 (after conv2)
__global__ __launch_bounds__(256) void k_ln(const float* __restrict__ gamma,
                                            const float* __restrict__ beta,
                                            int phase) {
    int b = blockIdx.y;
    int u = blockIdx.x * 8 + (threadIdx.x >> 5);
    int lane = threadIdx.x & 31;
    const float* Y = g_y + (size_t)b * NF * NU;
    float* O = (phase ? g_x2 : g_x1) + (size_t)b * NF * NU;
    float v[8];
    float s1 = 0.f, s2 = 0.f;
    #pragma unroll
    for (int i = 0; i < 8; i++) {
        int f = lane + 32 * i;
        float x = Y[(size_t)f * NU + u];
        v[i] = x;
        s1 += x;
        s2 += x * x;
    }
    #pragma unroll
    for (int o = 16; o > 0; o >>= 1) {
        s1 += __shfl_xor_sync(0xffffffffu, s1, o);
        s2 += __shfl_xor_sync(0xffffffffu, s2, o);
    }
    float m  = s1 * (1.f / 256.f);
    float var = s2 * (1.f / 256.f) - m * m;
    float rs = 1.f / sqrtf(var + EPS);
    float msk = (u < g_nseg[b]) ? 1.f : 0.f;
    #pragma unroll
    for (int i = 0; i < 8; i++) {
        int f = lane + 32 * i;
        O[(size_t)f * NU + u] = ((v[i] - m) * rs * gamma[f] + beta[f]) * msk;
    }
}

// ---------------- kernel 6: projection + ceil durations ----------------
__global__ __launch_bounds__(512) void k_proj(const float* __restrict__ pw,
                                              const float* __restrict__ pb) {
    int b = blockIdx.x;
    int u = threadIdx.x;
    __shared__ float w[NF];
    if (u < NF) w[u] = pw[u];
    __syncthreads();
    const float* X = g_x2 + (size_t)b * NF * NU;
    float acc = 0.f;
    #pragma unroll 8
    for (int f = 0; f < NF; f++) acc += X[(size_t)f * NU + u] * w[f];
    float dp = acc + pb[0];
    int ns = g_nseg[b];
    float d = (u < ns) ? ceilf(dp) : 0.f;
    g_dpred[b * NU + u] = (int)d;
}

// ---------------- kernel 7: per-batch prefix scan + scatter um2 ----------------
__global__ __launch_bounds__(512) void k_scan(int Tn) {
    int b = blockIdx.x;
    int u = threadIdx.x;
    __shared__ int sa[NU];
    __shared__ int sb[NU];
    int d = g_dpred[b * NU + u];
    sa[u] = d;
    __syncthreads();
    int* a = sa; int* bb = sb;
    for (int off = 1; off < NU; off <<= 1) {
        int v = a[u];
        if (u >= off) v += a[u - off];
        bb[u] = v;
        __syncthreads();
        int* t = a; a = bb; bb = t;
    }
    int csum = a[u];
    int prev = csum - d;
    int lo = prev > 0 ? prev : 0;
    int hi = csum < Tn ? csum : Tn;
    for (int p = lo; p < hi; p++)
        atomicAdd(&g_um2[b * Tn + p], u + 1);
}

// ---------------- kernel 8: expand + interp -> output ----------------
__global__ __launch_bounds__(256) void k_out(const float* __restrict__ mel,
                                             float* __restrict__ out,
                                             int Tn, int total) {
    int i = blockIdx.x * blockDim.x + threadIdx.x;
    if (i >= total) return;
    int perb = NOUTC * Tn;
    int b = i / perb;
    int r = i - b * perb;
    int ch = r / Tn;
    int t = r - ch * Tn;
    if (ch < 2 * NC) {
        int v = g_um2[b * Tn + t];
        int um = g_umax;
        int idx = v < um ? v : um;   // jax gather clamp semantics
        float val = 0.f;
        if (idx > 0) {
            const float* P = (ch < NC) ? g_uc : g_up;
            int c = (ch < NC) ? ch : ch - NC;
            val = P[((size_t)b * NC + c) * NU + idx - 1];
        }
        out[i] = val;
    } else {
        int mch = ch - 2 * NC;
        float scale = (float)(2048.0 / (double)Tn);
        float src = ((float)t + 0.5f) * scale - 0.5f;
        src = fminf(fmaxf(src, 0.f), (float)(NT - 1));
        int i0 = (int)floorf(src);
        int i1 = i0 + 1 < NT - 1 ? i0 + 1 : NT - 1;
        float w = src - (float)i0;
        const float* mr = mel + ((size_t)b * NMEL + mch) * NT;
        out[i] = mr[i0] * (1.f - w) + mr[i1] * w;
    }
}

// ---------------- launch ----------------
extern "C" void kernel_launch(void* const* d_in, const int* in_sizes, int n_in,
                              void* d_out, int out_size) {
    const float* emb_c  = (const float*)d_in[0];
    const float* emb_p  = (const float*)d_in[1];
    const float* mel    = (const float*)d_in[2];
    const float* g      = (const float*)d_in[3];
    const float* c1w    = (const float*)d_in[4];
    const float* c1b    = (const float*)d_in[5];
    const float* l1g    = (const float*)d_in[6];
    const float* l1b    = (const float*)d_in[7];
    const float* c2w    = (const float*)d_in[8];
    const float* c2b    = (const float*)d_in[9];
    const float* l2g    = (const float*)d_in[10];
    const float* l2b    = (const float*)d_in[11];
    const float* pw     = (const float*)d_in[12];
    const float* pb     = (const float*)d_in[13];
    const float* cw     = (const float*)d_in[14];
    const float* cb     = (const float*)d_in[15];
    const int*   ph     = (const int*)d_in[16];
    float* out = (float*)d_out;

    int Tn = out_size / (NB * NOUTC);

    k_zero<<<(NB * Tn + 255) / 256 + 1, 256>>>(Tn);
    k_dedup<<<NB, 1024>>>(ph);
    k_cond<<<NB, 256>>>(g, cw, cb);
    k_pool<<<dim3(2 * NC, NB), 256>>>(emb_c, emb_p);
    k_conv<<<dim3(NU / 64, NF / 64, NB), 256>>>(c1w, c1b, 0);
    k_ln<<<dim3(NU / 8, NB), 256>>>(l1g, l1b, 0);
    k_conv<<<dim3(NU / 64, NF / 64, NB), 256>>>(c2w, c2b, 1);
    k_ln<<<dim3(NU / 8, NB), 256>>>(l2g, l2b, 1);
    k_proj<<<NB, 512>>>(pw, pb);
    k_scan<<<NB, NU>>>(Tn);
    k_out<<<(out_size + 255) / 256, 256>>>(mel, out, Tn, out_size);
}

// round 3
// speedup vs baseline: 1.0984x; 1.0984x over previous
#include <cuda_runtime.h>
#include <math.h>
#include <stdint.h>

#define NB 16
#define NT 2048
#define NC 256
#define NF 256
#define NU 512
#define NMEL 80
#define NOUTC 592           // 2*NC + NMEL
#define KTOT 768            // NC * 3 taps
#define BK 8
#define NCHUNK (KTOT / BK)  // 96
#define UM2CAP 8192
#define EPS 1e-5f

typedef unsigned long long u64t;

// ---------------- static device scratch ----------------
__device__ int   g_starts[NB*NU];
__device__ int   g_dur[NB*NU];
__device__ int   g_nseg[NB];
__device__ int   g_umax;
__device__ float g_cgv[NB*NC];
__device__ float g_uc[NB*NC*NU];
__device__ float g_up[NB*NC*NU];
__device__ float g_x0[NB*NC*NU];        // conv1 input: (u_c + cond) * mask
__device__ float g_x1[NB*NF*NU];        // LN1 output * mask  -> conv2 input
__device__ int   g_dpred[NB*NU];
__device__ int   g_um2[NB*UM2CAP];

__device__ __forceinline__ u64t ffma2(u64t a, u64t b, u64t c) {
    u64t d;
    asm("fma.rn.f32x2 %0, %1, %2, %3;" : "=l"(d) : "l"(a), "l"(b), "l"(c));
    return d;
}
union F2U { u64t u; float2 f; };

// ---------------- kernel 0: zero um2 + umax ----------------
__global__ void k_zero(int Tn) {
    int i = blockIdx.x * blockDim.x + threadIdx.x;
    if (i == 0) g_umax = 0;
    if (i < NB * Tn) g_um2[i] = 0;
}

// ---------------- kernel 1: fused dedup (blocks 0..15) + cond (blocks 16..31) ----------------
__global__ __launch_bounds__(1024) void k_prep(const int* __restrict__ ph,
                                               const float* __restrict__ g,
                                               const float* __restrict__ cw,
                                               const float* __restrict__ cb) {
    int blk = blockIdx.x;
    if (blk < NB) {
        // ---- run-length dedup for batch blk ----
        int b = blk;
        const int* p = ph + (size_t)b * NT;
        int tid = threadIdx.x;
        int lane = tid & 31, wid = tid >> 5;
        int i0 = 2 * tid, i1 = 2 * tid + 1;
        int p0 = p[i0], p1 = p[i1];
        int pm1 = (i0 > 0) ? p[i0 - 1] : 0;
        int f0 = (i0 == 0) || (p0 != pm1);
        int f1 = (p1 != p0);
        int tsum = f0 + f1;
        // warp inclusive scan of tsum
        int ws = tsum;
        #pragma unroll
        for (int o = 1; o < 32; o <<= 1) {
            int y = __shfl_up_sync(0xffffffffu, ws, o);
            if (lane >= o) ws += y;
        }
        __shared__ int wt[32];
        if (lane == 31) wt[wid] = ws;
        __syncthreads();
        if (wid == 0) {
            int t = wt[lane];
            #pragma unroll
            for (int o = 1; o < 32; o <<= 1) {
                int y = __shfl_up_sync(0xffffffffu, t, o);
                if (lane >= o) t += y;
            }
            wt[lane] = t;
        }
        __syncthreads();
        int base = (wid ? wt[wid - 1] : 0) + (ws - tsum);  // exclusive thread prefix
        int incl0 = base + f0;
        int incl1 = base + f0 + f1;
        if (f0) g_starts[b * NU + incl0 - 1] = i0;
        if (f1) g_starts[b * NU + incl1 - 1] = i1;
        int ns = wt[31];
        __syncthreads();   // ensure g_starts visible block-wide
        for (int u = tid; u < NU; u += 1024) {
            if (u < ns) {
                int st = g_starts[b * NU + u];
                int en = (u + 1 < ns) ? g_starts[b * NU + u + 1] : NT;
                g_dur[b * NU + u] = en - st;
            } else {
                g_dur[b * NU + u] = 0;
            }
        }
        if (tid == 0) {
            g_nseg[b] = ns;
            atomicMax(&g_umax, ns);
        }
    } else {
        // ---- cond vector for batch blk-16 ----
        int b = blk - NB;
        int c = threadIdx.x;
        __shared__ float gs[NC];
        if (c < NC) gs[c] = g[(size_t)b * NC + c];
        __syncthreads();
        if (c < NC) {
            float acc = 0.f;
            const float* row = cw + (size_t)c * NC;
            #pragma unroll 8
            for (int gi = 0; gi < NC; gi++) acc += row[gi] * gs[gi];
            g_cgv[b * NC + c] = acc + cb[c];
        }
    }
}

// ---------------- kernel 2: mean pool (4 channels / block, flat float4 load) ----------------
__global__ __launch_bounds__(256) void k_pool(const float* __restrict__ ec,
                                              const float* __restrict__ ep) {
    int b  = blockIdx.y;
    int c0 = blockIdx.x * 4;                    // 0..508, groups never cross 256 boundary
    bool isC = (c0 < NC);
    const float* base = isC ? ec + ((size_t)b * NC + c0) * NT
                            : ep + ((size_t)b * NC + (c0 - NC)) * NT;
    __shared__ float rows[4][NT];
    const float4* s4 = (const float4*)base;
    float4* r4 = (float4*)&rows[0][0];
    #pragma unroll
    for (int i = threadIdx.x; i < 4 * NT / 4; i += 256) r4[i] = s4[i];
    __syncthreads();
    int ns = g_nseg[b];
    for (int u = threadIdx.x; u < NU; u += 256) {
        float m[4] = {0.f, 0.f, 0.f, 0.f};
        if (u < ns) {
            int st = g_starts[b * NU + u];
            int d  = g_dur[b * NU + u];
            float inv = 1.f / (float)d;
            #pragma unroll
            for (int r = 0; r < 4; r++) {
                float s = 0.f;
                for (int i = 0; i < d; i++) s += rows[r][st + i];
                m[r] = s * inv;
            }
        }
        #pragma unroll
        for (int r = 0; r < 4; r++) {
            int cc = c0 + r;
            if (isC) {
                float cond = g_cgv[b * NC + cc];
                g_uc[((size_t)b * NC + cc) * NU + u] = m[r];
                g_x0[((size_t)b * NC + cc) * NU + u] = (u < ns) ? (m[r] + cond) : 0.f;
            } else {
                g_up[((size_t)b * NC + (cc - NC)) * NU + u] = m[r];
            }
        }
    }
}

// ---------------- kernel 3/4: conv GEMM (256x64x768) + fused epilogue ----------------
// PHASE 0: X=g_x0, epilogue = bias+relu+LN1*mask -> g_x1
// PHASE 1: X=g_x1, epilogue = bias+relu+LN2*mask -> proj -> ceil -> g_dpred
template<int PHASE>
__global__ __launch_bounds__(256) void k_conv(const float* __restrict__ W,
                                              const float* __restrict__ bias,
                                              const float* __restrict__ gamma,
                                              const float* __restrict__ beta,
                                              const float* __restrict__ pw,
                                              const float* __restrict__ pb) {
    __shared__ float  As[2][BK][NF];       // As[buf][k][m]
    __shared__ float2 Bs[2][BK][64];       // duplicated (v,v) for broadcast f32x2

    int b  = blockIdx.y;
    int u0 = blockIdx.x * 64;
    int tid = threadIdx.x;
    int tn = tid >> 5;         // 0..7  col group (warp id)
    int tm = tid & 31;         // 0..31 row group (lane)
    const float* X = PHASE ? g_x1 : g_x0;
    const float* Xb = X + (size_t)b * NC * NU;

    u64t acc[4][8];
    #pragma unroll
    for (int i = 0; i < 4; i++)
        #pragma unroll
        for (int j = 0; j < 8; j++) acc[i][j] = 0ull;

    // prefetch registers
    float4 aA, aB;
    float  bv0, bv1;
    int kk = tn;                // B-loader k index
    int uu = tm * 2;            // B-loader col pair

    auto loadG = [&](int k0) {
        const float4* wr = (const float4*)&W[(size_t)tid * KTOT + k0];
        aA = wr[0];
        aB = wr[1];
        int kg  = k0 + kk;
        int c   = kg / 3;
        int tap = kg - 3 * c;
        const float* xr = Xb + (size_t)c * NU;
        int col = u0 + uu + tap - 1;
        bv0 = (col >= 0 && col < NU) ? xr[col] : 0.f;
        int col1 = col + 1;
        bv1 = (col1 >= 0 && col1 < NU) ? xr[col1] : 0.f;
    };
    auto storeS = [&](int buf) {
        As[buf][0][tid] = aA.x;  As[buf][1][tid] = aA.y;
        As[buf][2][tid] = aA.z;  As[buf][3][tid] = aA.w;
        As[buf][4][tid] = aB.x;  As[buf][5][tid] = aB.y;
        As[buf][6][tid] = aB.z;  As[buf][7][tid] = aB.w;
        Bs[buf][kk][uu]     = make_float2(bv0, bv0);
        Bs[buf][kk][uu + 1] = make_float2(bv1, bv1);
    };

    loadG(0);
    storeS(0);
    __syncthreads();

    for (int chunk = 0; chunk < NCHUNK; chunk++) {
        int buf = chunk & 1;
        if (chunk + 1 < NCHUNK) loadG((chunk + 1) * BK);
        #pragma unroll
        for (int k = 0; k < BK; k++) {
            const u64t* ap = (const u64t*)&As[buf][k][tm * 8];
            u64t a0 = ap[0], a1 = ap[1], a2 = ap[2], a3 = ap[3];
            const u64t* bp = (const u64t*)&Bs[buf][k][tn * 8];
            u64t b0 = bp[0], b1 = bp[1], b2 = bp[2], b3 = bp[3];
            u64t b4 = bp[4], b5 = bp[5], b6 = bp[6], b7 = bp[7];
            acc[0][0] = ffma2(a0, b0, acc[0][0]); acc[0][1] = ffma2(a0, b1, acc[0][1]);
            acc[0][2] = ffma2(a0, b2, acc[0][2]); acc[0][3] = ffma2(a0, b3, acc[0][3]);
            acc[0][4] = ffma2(a0, b4, acc[0][4]); acc[0][5] = ffma2(a0, b5, acc[0][5]);
            acc[0][6] = ffma2(a0, b6, acc[0][6]); acc[0][7] = ffma2(a0, b7, acc[0][7]);
            acc[1][0] = ffma2(a1, b0, acc[1][0]); acc[1][1] = ffma2(a1, b1, acc[1][1]);
            acc[1][2] = ffma2(a1, b2, acc[1][2]); acc[1][3] = ffma2(a1, b3, acc[1][3]);
            acc[1][4] = ffma2(a1, b4, acc[1][4]); acc[1][5] = ffma2(a1, b5, acc[1][5]);
            acc[1][6] = ffma2(a1, b6, acc[1][6]); acc[1][7] = ffma2(a1, b7, acc[1][7]);
            acc[2][0] = ffma2(a2, b0, acc[2][0]); acc[2][1] = ffma2(a2, b1, acc[2][1]);
            acc[2][2] = ffma2(a2, b2, acc[2][2]); acc[2][3] = ffma2(a2, b3, acc[2][3]);
            acc[2][4] = ffma2(a2, b4, acc[2][4]); acc[2][5] = ffma2(a2, b5, acc[2][5]);
            acc[2][6] = ffma2(a2, b6, acc[2][6]); acc[2][7] = ffma2(a2, b7, acc[2][7]);
            acc[3][0] = ffma2(a3, b0, acc[3][0]); acc[3][1] = ffma2(a3, b1, acc[3][1]);
            acc[3][2] = ffma2(a3, b2, acc[3][2]); acc[3][3] = ffma2(a3, b3, acc[3][3]);
            acc[3][4] = ffma2(a3, b4, acc[3][4]); acc[3][5] = ffma2(a3, b5, acc[3][5]);
            acc[3][6] = ffma2(a3, b6, acc[3][6]); acc[3][7] = ffma2(a3, b7, acc[3][7]);
        }
        if (chunk + 1 < NCHUNK) storeS(buf ^ 1);
        __syncthreads();
    }

    // ---- epilogue ----
    int fbase = tm * 8;
    float v[8][8];
    #pragma unroll
    for (int p = 0; p < 4; p++)
        #pragma unroll
        for (int j = 0; j < 8; j++) {
            F2U t; t.u = acc[p][j];
            v[2 * p][j]     = t.f.x;
            v[2 * p + 1][j] = t.f.y;
        }
    float s1[8], s2[8];
    #pragma unroll
    for (int j = 0; j < 8; j++) { s1[j] = 0.f; s2[j] = 0.f; }
    #pragma unroll
    for (int i = 0; i < 8; i++) {
        float bs = bias[fbase + i];
        #pragma unroll
        for (int j = 0; j < 8; j++) {
            float x = fmaxf(v[i][j] + bs, 0.f);
            v[i][j] = x;
            s1[j] += x;
            s2[j] += x * x;
        }
    }
    #pragma unroll
    for (int o = 16; o > 0; o >>= 1) {
        #pragma unroll
        for (int j = 0; j < 8; j++) {
            s1[j] += __shfl_xor_sync(0xffffffffu, s1[j], o);
            s2[j] += __shfl_xor_sync(0xffffffffu, s2[j], o);
        }
    }
    int ns = g_nseg[b];
    float mean[8], rs[8], msk[8];
    #pragma unroll
    for (int j = 0; j < 8; j++) {
        float m  = s1[j] * (1.f / 256.f);
        float vv = s2[j] * (1.f / 256.f) - m * m;
        mean[j] = m;
        rs[j]   = 1.f / sqrtf(vv + EPS);
        msk[j]  = (u0 + tn * 8 + j < ns) ? 1.f : 0.f;
    }

    if (PHASE == 0) {
        #pragma unroll
        for (int i = 0; i < 8; i++) {
            int f = fbase + i;
            float ga = gamma[f], be = beta[f];
            float o[8];
            #pragma unroll
            for (int j = 0; j < 8; j++)
                o[j] = ((v[i][j] - mean[j]) * rs[j] * ga + be) * msk[j];
            float* dst = g_x1 + ((size_t)b * NF + f) * NU + u0 + tn * 8;
            *(float4*)(dst)     = make_float4(o[0], o[1], o[2], o[3]);
            *(float4*)(dst + 4) = make_float4(o[4], o[5], o[6], o[7]);
        }
    } else {
        float dp[8];
        #pragma unroll
        for (int j = 0; j < 8; j++) dp[j] = 0.f;
        #pragma unroll
        for (int i = 0; i < 8; i++) {
            int f = fbase + i;
            float ga = gamma[f], be = beta[f];
            float w  = pw[f];
            #pragma unroll
            for (int j = 0; j < 8; j++) {
                float nv = ((v[i][j] - mean[j]) * rs[j] * ga + be) * msk[j];
                dp[j] += nv * w;
            }
        }
        #pragma unroll
        for (int o = 16; o > 0; o >>= 1)
            #pragma unroll
            for (int j = 0; j < 8; j++)
                dp[j] += __shfl_xor_sync(0xffffffffu, dp[j], o);
        float pbv = pb[0];
        #pragma unroll
        for (int j = 0; j < 8; j++) {
            if (tm == j) {
                int u = u0 + tn * 8 + j;
                float d = (u < ns) ? ceilf(dp[j] + pbv) : 0.f;
                g_dpred[b * NU + u] = (int)d;
            }
        }
    }
}

// ---------------- kernel 5: per-batch prefix scan + scatter um2 ----------------
__global__ __launch_bounds__(512) void k_scan(int Tn) {
    int b = blockIdx.x;
    int u = threadIdx.x;
    int lane = u & 31, wid = u >> 5;
    int d = g_dpred[b * NU + u];
    int x = d;
    #pragma unroll
    for (int o = 1; o < 32; o <<= 1) {
        int y = __shfl_up_sync(0xffffffffu, x, o);
        if (lane >= o) x += y;
    }
    __shared__ int wt[16];
    if (lane == 31) wt[wid] = x;
    __syncthreads();
    if (u < 16) {
        int t = wt[u];
        #pragma unroll
        for (int o = 1; o < 16; o <<= 1) {
            int y = __shfl_up_sync(0xffffu, t, o);
            if (u >= o) t += y;
        }
        wt[u] = t;
    }
    __syncthreads();
    int csum = x + (wid ? wt[wid - 1] : 0);
    int prev = csum - d;
    int lo = prev > 0 ? prev : 0;
    int hi = csum < Tn ? csum : Tn;
    for (int p = lo; p < hi; p++)
        atomicAdd(&g_um2[b * Tn + p], u + 1);
}

// ---------------- kernel 6: expand + interp -> output ----------------
__global__ __launch_bounds__(256) void k_out(const float* __restrict__ mel,
                                             float* __restrict__ out,
                                             int Tn, int total) {
    int i = blockIdx.x * blockDim.x + threadIdx.x;
    if (i >= total) return;
    int perb = NOUTC * Tn;
    int b = i / perb;
    int r = i - b * perb;
    int ch = r / Tn;
    int t = r - ch * Tn;
    if (ch < 2 * NC) {
        int v = g_um2[b * Tn + t];
        int um = g_umax;
        int idx = v < um ? v : um;   // jax gather clamp semantics
        float val = 0.f;
        if (idx > 0) {
            const float* P = (ch < NC) ? g_uc : g_up;
            int c = (ch < NC) ? ch : ch - NC;
            val = P[((size_t)b * NC + c) * NU + idx - 1];
        }
        out[i] = val;
    } else {
        int mch = ch - 2 * NC;
        float scale = (float)(2048.0 / (double)Tn);
        float src = ((float)t + 0.5f) * scale - 0.5f;
        src = fminf(fmaxf(src, 0.f), (float)(NT - 1));
        int i0 = (int)floorf(src);
        int i1 = i0 + 1 < NT - 1 ? i0 + 1 : NT - 1;
        float w = src - (float)i0;
        const float* mr = mel + ((size_t)b * NMEL + mch) * NT;
        out[i] = mr[i0] * (1.f - w) + mr[i1] * w;
    }
}

// ---------------- launch ----------------
extern "C" void kernel_launch(void* const* d_in, const int* in_sizes, int n_in,
                              void* d_out, int out_size) {
    const float* emb_c  = (const float*)d_in[0];
    const float* emb_p  = (const float*)d_in[1];
    const float* mel    = (const float*)d_in[2];
    const float* g      = (const float*)d_in[3];
    const float* c1w    = (const float*)d_in[4];
    const float* c1b    = (const float*)d_in[5];
    const float* l1g    = (const float*)d_in[6];
    const float* l1b    = (const float*)d_in[7];
    const float* c2w    = (const float*)d_in[8];
    const float* c2b    = (const float*)d_in[9];
    const float* l2g    = (const float*)d_in[10];
    const float* l2b    = (const float*)d_in[11];
    const float* pw     = (const float*)d_in[12];
    const float* pb     = (const float*)d_in[13];
    const float* cw     = (const float*)d_in[14];
    const float* cb     = (const float*)d_in[15];
    const int*   ph     = (const int*)d_in[16];
    float* out = (float*)d_out;

    int Tn = out_size / (NB * NOUTC);

    k_zero<<<(NB * Tn + 255) / 256 + 1, 256>>>(Tn);
    k_prep<<<2 * NB, 1024>>>(ph, g, cw, cb);
    k_pool<<<dim3(2 * NC / 4, NB), 256>>>(emb_c, emb_p);
    k_conv<0><<<dim3(NU / 64, NB), 256>>>(c1w, c1b, l1g, l1b, pw, pb);
    k_conv<1><<<dim3(NU / 64, NB), 256>>>(c2w, c2b, l2g, l2b, pw, pb);
    k_scan<<<NB, NU>>>(Tn);
    k_out<<<(out_size + 255) / 256, 256>>>(mel, out, Tn, out_size);
}

// round 4
// speedup vs baseline: 1.2469x; 1.1352x over previous
#include <cuda_runtime.h>
#include <math.h>
#include <stdint.h>

#define NB 16
#define NT 2048
#define NC 256
#define NF 256
#define NU 512
#define NMEL 80
#define NOUTC 592           // 2*NC + NMEL
#define KTOT 768            // NC * 3 taps
#define BK 8
#define NCHUNK (KTOT / BK)  // 96
#define UM2CAP 8192
#define EPS 1e-5f

typedef unsigned long long u64t;

// ---------------- static device scratch ----------------
__device__ int   g_starts[NB*NU];
__device__ int   g_dur[NB*NU];
__device__ int   g_nseg[NB];
__device__ int   g_umax;
__device__ float g_cgv[NB*NC];
__device__ float g_uc[NB*NC*NU];
__device__ float g_up[NB*NC*NU];
__device__ float g_x0[NB*NC*NU];        // conv1 input: (u_c + cond) * mask
__device__ float g_x1[NB*NF*NU];        // LN1 output * mask  -> conv2 input
__device__ int   g_dpred[NB*NU];
__device__ int   g_um2[NB*UM2CAP];

__device__ __forceinline__ u64t ffma2(u64t a, u64t b, u64t c) {
    u64t d;
    asm("fma.rn.f32x2 %0, %1, %2, %3;" : "=l"(d) : "l"(a), "l"(b), "l"(c));
    return d;
}
__device__ __forceinline__ u64t dup2(float v) {
    u64t d;
    asm("mov.b64 %0, {%1, %1};" : "=l"(d) : "f"(v));
    return d;
}
union F2U { u64t u; float2 f; };

// ---------------- kernel 0: zero um2 + umax ----------------
__global__ void k_zero(int Tn) {
    int i = blockIdx.x * blockDim.x + threadIdx.x;
    if (i == 0) g_umax = 0;
    if (i < NB * Tn) g_um2[i] = 0;
}

// ---------------- kernel 1: fused dedup (blocks 0..15) + cond (blocks 16..31) ----------------
__global__ __launch_bounds__(1024) void k_prep(const int* __restrict__ ph,
                                               const float* __restrict__ g,
                                               const float* __restrict__ cw,
                                               const float* __restrict__ cb) {
    int blk = blockIdx.x;
    if (blk < NB) {
        int b = blk;
        const int* p = ph + (size_t)b * NT;
        int tid = threadIdx.x;
        int lane = tid & 31, wid = tid >> 5;
        int i0 = 2 * tid, i1 = 2 * tid + 1;
        int p0 = p[i0], p1 = p[i1];
        int pm1 = (i0 > 0) ? p[i0 - 1] : 0;
        int f0 = (i0 == 0) || (p0 != pm1);
        int f1 = (p1 != p0);
        int tsum = f0 + f1;
        int ws = tsum;
        #pragma unroll
        for (int o = 1; o < 32; o <<= 1) {
            int y = __shfl_up_sync(0xffffffffu, ws, o);
            if (lane >= o) ws += y;
        }
        __shared__ int wt[32];
        if (lane == 31) wt[wid] = ws;
        __syncthreads();
        if (wid == 0) {
            int t = wt[lane];
            #pragma unroll
            for (int o = 1; o < 32; o <<= 1) {
                int y = __shfl_up_sync(0xffffffffu, t, o);
                if (lane >= o) t += y;
            }
            wt[lane] = t;
        }
        __syncthreads();
        int base = (wid ? wt[wid - 1] : 0) + (ws - tsum);
        int incl0 = base + f0;
        int incl1 = base + f0 + f1;
        if (f0) g_starts[b * NU + incl0 - 1] = i0;
        if (f1) g_starts[b * NU + incl1 - 1] = i1;
        int ns = wt[31];
        __syncthreads();
        for (int u = tid; u < NU; u += 1024) {
            if (u < ns) {
                int st = g_starts[b * NU + u];
                int en = (u + 1 < ns) ? g_starts[b * NU + u + 1] : NT;
                g_dur[b * NU + u] = en - st;
            } else {
                g_dur[b * NU + u] = 0;
            }
        }
        if (tid == 0) {
            g_nseg[b] = ns;
            atomicMax(&g_umax, ns);
        }
    } else {
        int b = blk - NB;
        int c = threadIdx.x;
        __shared__ float gs[NC];
        if (c < NC) gs[c] = g[(size_t)b * NC + c];
        __syncthreads();
        if (c < NC) {
            float acc = 0.f;
            const float* row = cw + (size_t)c * NC;
            #pragma unroll 8
            for (int gi = 0; gi < NC; gi++) acc += row[gi] * gs[gi];
            g_cgv[b * NC + c] = acc + cb[c];
        }
    }
}

// ---------------- kernel 2: mean pool (4 channels / block) ----------------
__global__ __launch_bounds__(256) void k_pool(const float* __restrict__ ec,
                                              const float* __restrict__ ep) {
    int b  = blockIdx.y;
    int c0 = blockIdx.x * 4;
    bool isC = (c0 < NC);
    const float* base = isC ? ec + ((size_t)b * NC + c0) * NT
                            : ep + ((size_t)b * NC + (c0 - NC)) * NT;
    __shared__ float rows[4][NT];
    const float4* s4 = (const float4*)base;
    float4* r4 = (float4*)&rows[0][0];
    #pragma unroll
    for (int i = threadIdx.x; i < 4 * NT / 4; i += 256) r4[i] = s4[i];
    __syncthreads();
    int ns = g_nseg[b];
    for (int u = threadIdx.x; u < NU; u += 256) {
        float m[4] = {0.f, 0.f, 0.f, 0.f};
        if (u < ns) {
            int st = g_starts[b * NU + u];
            int d  = g_dur[b * NU + u];
            float inv = 1.f / (float)d;
            #pragma unroll
            for (int r = 0; r < 4; r++) {
                float s = 0.f;
                for (int i = 0; i < d; i++) s += rows[r][st + i];
                m[r] = s * inv;
            }
        }
        #pragma unroll
        for (int r = 0; r < 4; r++) {
            int cc = c0 + r;
            if (isC) {
                float cond = g_cgv[b * NC + cc];
                g_uc[((size_t)b * NC + cc) * NU + u] = m[r];
                g_x0[((size_t)b * NC + cc) * NU + u] = (u < ns) ? (m[r] + cond) : 0.f;
            } else {
                g_up[((size_t)b * NC + (cc - NC)) * NU + u] = m[r];
            }
        }
    }
}

// ---------------- conv GEMM (256x64x768) + fused epilogue ----------------
// Conflict-free LDS: thread rows = {tm*4..+3, 128+tm*4..+3}. B read distinct,
// duplicated to (v,v) pairs in registers via mov.b64.
// PHASE 0: X=g_x0, epilogue = bias+relu+LN1*mask -> g_x1
// PHASE 1: X=g_x1, epilogue = bias+relu+LN2*mask -> proj -> ceil -> g_dpred
template<int PHASE>
__global__ __launch_bounds__(256) void k_conv(const float* __restrict__ W,
                                              const float* __restrict__ bias,
                                              const float* __restrict__ gamma,
                                              const float* __restrict__ beta,
                                              const float* __restrict__ pw,
                                              const float* __restrict__ pb) {
    __shared__ float As[2][BK][NF];        // As[buf][k][m]
    __shared__ float Bs[2][BK][64];        // distinct values

    int b  = blockIdx.y;
    int u0 = blockIdx.x * 64;
    int tid = threadIdx.x;
    int tn = tid >> 5;         // 0..7  col group (warp id) -> cols u0+tn*8..+7
    int tm = tid & 31;         // lane  -> rows tm*4..+3 and 128+tm*4..+3
    const float* X = PHASE ? g_x1 : g_x0;
    const float* Xb = X + (size_t)b * NC * NU;

    u64t acc[4][8];
    #pragma unroll
    for (int i = 0; i < 4; i++)
        #pragma unroll
        for (int j = 0; j < 8; j++) acc[i][j] = 0ull;

    // prefetch registers
    float4 aA, aB;
    float  bv0, bv1;
    int bkk = tid >> 5;          // B loader: k index 0..7
    int bnn = (tid & 31) * 2;    // B loader: col pair 0..62

    auto loadG = [&](int k0) {
        const float4* wr = (const float4*)&W[(size_t)tid * KTOT + k0];
        aA = wr[0];
        aB = wr[1];
        int kg  = k0 + bkk;
        int c   = kg / 3;
        int tap = kg - 3 * c;
        const float* xr = Xb + (size_t)c * NU;
        int col = u0 + bnn + tap - 1;
        bv0 = (col >= 0 && col < NU) ? xr[col] : 0.f;
        int col1 = col + 1;
        bv1 = (col1 >= 0 && col1 < NU) ? xr[col1] : 0.f;
    };
    auto storeS = [&](int buf) {
        As[buf][0][tid] = aA.x;  As[buf][1][tid] = aA.y;
        As[buf][2][tid] = aA.z;  As[buf][3][tid] = aA.w;
        As[buf][4][tid] = aB.x;  As[buf][5][tid] = aB.y;
        As[buf][6][tid] = aB.z;  As[buf][7][tid] = aB.w;
        *(float2*)&Bs[buf][bkk][bnn] = make_float2(bv0, bv1);
    };

    loadG(0);
    storeS(0);
    __syncthreads();

    for (int chunk = 0; chunk < NCHUNK; chunk++) {
        int buf = chunk & 1;
        if (chunk + 1 < NCHUNK) loadG((chunk + 1) * BK);
        #pragma unroll
        for (int k = 0; k < BK; k++) {
            ulonglong2 aa0 = *(const ulonglong2*)&As[buf][k][tm * 4];
            ulonglong2 aa1 = *(const ulonglong2*)&As[buf][k][128 + tm * 4];
            u64t a0 = aa0.x, a1 = aa0.y, a2 = aa1.x, a3 = aa1.y;
            float4 bf0 = *(const float4*)&Bs[buf][k][tn * 8];
            float4 bf1 = *(const float4*)&Bs[buf][k][tn * 8 + 4];
            u64t b0 = dup2(bf0.x), b1 = dup2(bf0.y), b2 = dup2(bf0.z), b3 = dup2(bf0.w);
            u64t b4 = dup2(bf1.x), b5 = dup2(bf1.y), b6 = dup2(bf1.z), b7 = dup2(bf1.w);
            acc[0][0] = ffma2(a0, b0, acc[0][0]); acc[0][1] = ffma2(a0, b1, acc[0][1]);
            acc[0][2] = ffma2(a0, b2, acc[0][2]); acc[0][3] = ffma2(a0, b3, acc[0][3]);
            acc[0][4] = ffma2(a0, b4, acc[0][4]); acc[0][5] = ffma2(a0, b5, acc[0][5]);
            acc[0][6] = ffma2(a0, b6, acc[0][6]); acc[0][7] = ffma2(a0, b7, acc[0][7]);
            acc[1][0] = ffma2(a1, b0, acc[1][0]); acc[1][1] = ffma2(a1, b1, acc[1][1]);
            acc[1][2] = ffma2(a1, b2, acc[1][2]); acc[1][3] = ffma2(a1, b3, acc[1][3]);
            acc[1][4] = ffma2(a1, b4, acc[1][4]); acc[1][5] = ffma2(a1, b5, acc[1][5]);
            acc[1][6] = ffma2(a1, b6, acc[1][6]); acc[1][7] = ffma2(a1, b7, acc[1][7]);
            acc[2][0] = ffma2(a2, b0, acc[2][0]); acc[2][1] = ffma2(a2, b1, acc[2][1]);
            acc[2][2] = ffma2(a2, b2, acc[2][2]); acc[2][3] = ffma2(a2, b3, acc[2][3]);
            acc[2][4] = ffma2(a2, b4, acc[2][4]); acc[2][5] = ffma2(a2, b5, acc[2][5]);
            acc[2][6] = ffma2(a2, b6, acc[2][6]); acc[2][7] = ffma2(a2, b7, acc[2][7]);
            acc[3][0] = ffma2(a3, b0, acc[3][0]); acc[3][1] = ffma2(a3, b1, acc[3][1]);
            acc[3][2] = ffma2(a3, b2, acc[3][2]); acc[3][3] = ffma2(a3, b3, acc[3][3]);
            acc[3][4] = ffma2(a3, b4, acc[3][4]); acc[3][5] = ffma2(a3, b5, acc[3][5]);
            acc[3][6] = ffma2(a3, b6, acc[3][6]); acc[3][7] = ffma2(a3, b7, acc[3][7]);
        }
        if (chunk + 1 < NCHUNK) storeS(buf ^ 1);
        __syncthreads();
    }

    // ---- epilogue ----
    // rows: i<4 -> tm*4+i ; i>=4 -> 128+tm*4+(i-4)
    float v[8][8];
    #pragma unroll
    for (int p = 0; p < 4; p++)
        #pragma unroll
        for (int j = 0; j < 8; j++) {
            F2U t; t.u = acc[p][j];
            v[2 * p][j]     = t.f.x;
            v[2 * p + 1][j] = t.f.y;
        }
    int frow[8];
    #pragma unroll
    for (int i = 0; i < 8; i++)
        frow[i] = (i < 4) ? (tm * 4 + i) : (128 + tm * 4 + (i - 4));

    float s1[8], s2[8];
    #pragma unroll
    for (int j = 0; j < 8; j++) { s1[j] = 0.f; s2[j] = 0.f; }
    #pragma unroll
    for (int i = 0; i < 8; i++) {
        float bs = bias[frow[i]];
        #pragma unroll
        for (int j = 0; j < 8; j++) {
            float x = fmaxf(v[i][j] + bs, 0.f);
            v[i][j] = x;
            s1[j] += x;
            s2[j] += x * x;
        }
    }
    #pragma unroll
    for (int o = 16; o > 0; o >>= 1) {
        #pragma unroll
        for (int j = 0; j < 8; j++) {
            s1[j] += __shfl_xor_sync(0xffffffffu, s1[j], o);
            s2[j] += __shfl_xor_sync(0xffffffffu, s2[j], o);
        }
    }
    int ns = g_nseg[b];
    float mean[8], rs[8], msk[8];
    #pragma unroll
    for (int j = 0; j < 8; j++) {
        float m  = s1[j] * (1.f / 256.f);
        float vv = s2[j] * (1.f / 256.f) - m * m;
        mean[j] = m;
        rs[j]   = 1.f / sqrtf(vv + EPS);
        msk[j]  = (u0 + tn * 8 + j < ns) ? 1.f : 0.f;
    }

    if (PHASE == 0) {
        #pragma unroll
        for (int i = 0; i < 8; i++) {
            int f = frow[i];
            float ga = gamma[f], be = beta[f];
            float o[8];
            #pragma unroll
            for (int j = 0; j < 8; j++)
                o[j] = ((v[i][j] - mean[j]) * rs[j] * ga + be) * msk[j];
            float* dst = g_x1 + ((size_t)b * NF + f) * NU + u0 + tn * 8;
            *(float4*)(dst)     = make_float4(o[0], o[1], o[2], o[3]);
            *(float4*)(dst + 4) = make_float4(o[4], o[5], o[6], o[7]);
        }
    } else {
        float dp[8];
        #pragma unroll
        for (int j = 0; j < 8; j++) dp[j] = 0.f;
        #pragma unroll
        for (int i = 0; i < 8; i++) {
            int f = frow[i];
            float ga = gamma[f], be = beta[f];
            float w  = pw[f];
            #pragma unroll
            for (int j = 0; j < 8; j++) {
                float nv = ((v[i][j] - mean[j]) * rs[j] * ga + be) * msk[j];
                dp[j] += nv * w;
            }
        }
        #pragma unroll
        for (int o = 16; o > 0; o >>= 1)
            #pragma unroll
            for (int j = 0; j < 8; j++)
                dp[j] += __shfl_xor_sync(0xffffffffu, dp[j], o);
        float pbv = pb[0];
        #pragma unroll
        for (int j = 0; j < 8; j++) {
            if (tm == j) {
                int u = u0 + tn * 8 + j;
                float d = (u < ns) ? ceilf(dp[j] + pbv) : 0.f;
                g_dpred[b * NU + u] = (int)d;
            }
        }
    }
}

// ---------------- kernel 5: per-batch prefix scan + scatter um2 ----------------
__global__ __launch_bounds__(512) void k_scan(int Tn) {
    int b = blockIdx.x;
    int u = threadIdx.x;
    int lane = u & 31, wid = u >> 5;
    int d = g_dpred[b * NU + u];
    int x = d;
    #pragma unroll
    for (int o = 1; o < 32; o <<= 1) {
        int y = __shfl_up_sync(0xffffffffu, x, o);
        if (lane >= o) x += y;
    }
    __shared__ int wt[16];
    if (lane == 31) wt[wid] = x;
    __syncthreads();
    if (u < 16) {
        int t = wt[u];
        #pragma unroll
        for (int o = 1; o < 16; o <<= 1) {
            int y = __shfl_up_sync(0xffffu, t, o);
            if (u >= o) t += y;
        }
        wt[u] = t;
    }
    __syncthreads();
    int csum = x + (wid ? wt[wid - 1] : 0);
    int prev = csum - d;
    int lo = prev > 0 ? prev : 0;
    int hi = csum < Tn ? csum : Tn;
    for (int p = lo; p < hi; p++)
        atomicAdd(&g_um2[b * Tn + p], u + 1);
}

// ---------------- kernel 6: expand + interp -> output ----------------
__global__ __launch_bounds__(256) void k_out(const float* __restrict__ mel,
                                             float* __restrict__ out,
                                             int Tn, int total) {
    int i = blockIdx.x * blockDim.x + threadIdx.x;
    if (i >= total) return;
    int perb = NOUTC * Tn;
    int b = i / perb;
    int r = i - b * perb;
    int ch = r / Tn;
    int t = r - ch * Tn;
    if (ch < 2 * NC) {
        int v = g_um2[b * Tn + t];
        int um = g_umax;
        int idx = v < um ? v : um;   // jax gather clamp semantics
        float val = 0.f;
        if (idx > 0) {
            const float* P = (ch < NC) ? g_uc : g_up;
            int c = (ch < NC) ? ch : ch - NC;
            val = P[((size_t)b * NC + c) * NU + idx - 1];
        }
        out[i] = val;
    } else {
        int mch = ch - 2 * NC;
        float scale = (float)(2048.0 / (double)Tn);
        float src = ((float)t + 0.5f) * scale - 0.5f;
        src = fminf(fmaxf(src, 0.f), (float)(NT - 1));
        int i0 = (int)floorf(src);
        int i1 = i0 + 1 < NT - 1 ? i0 + 1 : NT - 1;
        float w = src - (float)i0;
        const float* mr = mel + ((size_t)b * NMEL + mch) * NT;
        out[i] = mr[i0] * (1.f - w) + mr[i1] * w;
    }
}

// ---------------- launch ----------------
extern "C" void kernel_launch(void* const* d_in, const int* in_sizes, int n_in,
                              void* d_out, int out_size) {
    const float* emb_c  = (const float*)d_in[0];
    const float* emb_p  = (const float*)d_in[1];
    const float* mel    = (const float*)d_in[2];
    const float* g      = (const float*)d_in[3];
    const float* c1w    = (const float*)d_in[4];
    const float* c1b    = (const float*)d_in[5];
    const float* l1g    = (const float*)d_in[6];
    const float* l1b    = (const float*)d_in[7];
    const float* c2w    = (const float*)d_in[8];
    const float* c2b    = (const float*)d_in[9];
    const float* l2g    = (const float*)d_in[10];
    const float* l2b    = (const float*)d_in[11];
    const float* pw     = (const float*)d_in[12];
    const float* pb     = (const float*)d_in[13];
    const float* cw     = (const float*)d_in[14];
    const float* cb     = (const float*)d_in[15];
    const int*   ph     = (const int*)d_in[16];
    float* out = (float*)d_out;

    int Tn = out_size / (NB * NOUTC);

    k_zero<<<(NB * Tn + 255) / 256 + 1, 256>>>(Tn);
    k_prep<<<2 * NB, 1024>>>(ph, g, cw, cb);
    k_pool<<<dim3(2 * NC / 4, NB), 256>>>(emb_c, emb_p);
    k_conv<0><<<dim3(NU / 64, NB), 256>>>(c1w, c1b, l1g, l1b, pw, pb);
    k_conv<1><<<dim3(NU / 64, NB), 256>>>(c2w, c2b, l2g, l2b, pw, pb);
    k_scan<<<NB, NU>>>(Tn);
    k_out<<<(out_size + 255) / 256, 256>>>(mel, out, Tn, out_size);
}